// round 6
// baseline (speedup 1.0000x reference)
#include <cuda_runtime.h>
#include <math.h>

#define B_ 64
#define S_ 4096
#define H_ 512
#define A_ 256
#define IN_ 256
#define NCHUNK 32
#define CHUNK (S_ / NCHUNK)            // 128 rows per block
#define WARPS_B 8
#define ROWS_PER_WARP (CHUNK / WARPS_B) // 16

// Scratch (no allocations allowed) ------------------------------------------
__device__ float g_Q[B_ * A_];             // Q = x@Wq + bq
__device__ float g_qt[B_ * H_];            // folded query  q~ = Q @ Wk^T
__device__ float g_cst[B_];                // Q . bk
__device__ float g_pm[B_ * NCHUNK];        // per-chunk running max
__device__ float g_pl[B_ * NCHUNK];        // per-chunk exp-sum
__device__ float g_pc[B_ * NCHUNK * H_];   // per-chunk weighted hidden sum (4 MB)
__device__ float g_WvT[A_ * H_];           // transposed Wv (A-major)

// ---------------------------------------------------------------------------
// Kernel A1: Q = x@Wq + bq  and  cst[b] = Q[b] . bk
// 8 independent chains, modest unroll (NO flat 256-LDG unroll — that spilled).
__global__ __launch_bounds__(256) void q_kernel(
    const float* __restrict__ x, const float* __restrict__ Wq,
    const float* __restrict__ bq, const float* __restrict__ bk)
{
    const int b = blockIdx.x;
    const int a = threadIdx.x;
    __shared__ float shP[A_];

    const float* xr = x + b * IN_;
    float acc[8];
    #pragma unroll
    for (int k = 0; k < 8; ++k) acc[k] = 0.f;

    #pragma unroll 4
    for (int i = 0; i < IN_; i += 8) {
        #pragma unroll
        for (int k = 0; k < 8; ++k)
            acc[k] = fmaf(xr[i + k], Wq[(i + k) * A_ + a], acc[k]);
    }
    float q = 0.f;
    #pragma unroll
    for (int k = 0; k < 8; ++k) q += acc[k];
    q += bq[a];

    g_Q[b * A_ + a] = q;
    shP[a] = q * bk[a];
    __syncthreads();

    for (int s = 128; s > 0; s >>= 1) {
        if (a < s) shP[a] += shP[a + s];
        __syncthreads();
    }
    if (a == 0) g_cst[b] = shP[0];
}

// ---------------------------------------------------------------------------
// Kernel A2: q~[b,h] = sum_a Q[b,a] * Wk[h,a]  — one WARP per output element.
__global__ __launch_bounds__(256) void qt_kernel(const float* __restrict__ Wk)
{
    const int gw   = blockIdx.x * WARPS_B + (threadIdx.x >> 5);
    const int lane = threadIdx.x & 31;
    const int b = gw >> 9;          // /512
    const int h = gw & (H_ - 1);    // %512

    const float* wr = Wk + h * A_;
    const float* qr = g_Q + b * A_;
    float acc = 0.f;
    #pragma unroll
    for (int j = 0; j < A_ / 32; ++j) {
        const int a = j * 32 + lane;
        acc = fmaf(qr[a], wr[a], acc);
    }
    #pragma unroll
    for (int o = 16; o > 0; o >>= 1)
        acc += __shfl_xor_sync(0xffffffffu, acc, o);
    if (lane == 0) g_qt[b * H_ + h] = acc;
}

// ---------------------------------------------------------------------------
// Kernel A3: Wv transpose -> g_WvT[a][h]
__global__ __launch_bounds__(256) void wvT_kernel(const float* __restrict__ Wv)
{
    __shared__ float tile[32][33];
    const int a0 = blockIdx.x * 32;
    const int h0 = blockIdx.y * 32;
    const int tx = threadIdx.x;      // 0..31
    const int ty = threadIdx.y;      // 0..7

    #pragma unroll
    for (int i = 0; i < 4; ++i) {
        const int h = h0 + ty + i * 8;
        tile[ty + i * 8][tx] = Wv[h * A_ + a0 + tx];
    }
    __syncthreads();
    #pragma unroll
    for (int i = 0; i < 4; ++i) {
        const int a = a0 + ty + i * 8;
        g_WvT[a * H_ + h0 + tx] = tile[tx][ty + i * 8];
    }
}

// ---------------------------------------------------------------------------
// Kernel B: streaming online-softmax pass over history_h.
// grid = (NCHUNK, B_) = 2048 CTAs, block = 256 (8 warps, 16 rows each),
// register-resident query, pipelined row loads (8 LDG.128 in flight/warp).
__global__ __launch_bounds__(256) void attn_pass_kernel(const float* __restrict__ hist)
{
    const int b     = blockIdx.y;
    const int chunk = blockIdx.x;
    const int tid   = threadIdx.x;
    const int w     = tid >> 5;
    const int lane  = tid & 31;

    float4 q4[4];
    const float4* qv = (const float4*)(g_qt + b * H_);
    #pragma unroll
    for (int j = 0; j < 4; ++j) q4[j] = qv[j * 32 + lane];

    const float cb = g_cst[b];
    const float inv_scale = 0.0625f; // 1/sqrt(256)

    float m = -INFINITY, l = 0.f;
    float4 acc[4];
    #pragma unroll
    for (int j = 0; j < 4; ++j) acc[j] = make_float4(0.f, 0.f, 0.f, 0.f);

    const int s0 = chunk * CHUNK + w * ROWS_PER_WARP;
    const float4* rowp = (const float4*)(hist + ((size_t)b * S_ + s0) * H_);
    const int row_stride4 = H_ / 4;

    float4 h4[4], n4[4];
    #pragma unroll
    for (int j = 0; j < 4; ++j) h4[j] = rowp[j * 32 + lane];

    for (int r = 0; r < ROWS_PER_WARP; ++r) {
        if (r < ROWS_PER_WARP - 1) {
            const float4* np = rowp + (size_t)(r + 1) * row_stride4;
            #pragma unroll
            for (int j = 0; j < 4; ++j) n4[j] = np[j * 32 + lane];
        }

        float dot = 0.f;
        #pragma unroll
        for (int j = 0; j < 4; ++j) {
            dot = fmaf(h4[j].x, q4[j].x, dot);
            dot = fmaf(h4[j].y, q4[j].y, dot);
            dot = fmaf(h4[j].z, q4[j].z, dot);
            dot = fmaf(h4[j].w, q4[j].w, dot);
        }
        #pragma unroll
        for (int o = 16; o > 0; o >>= 1)
            dot += __shfl_xor_sync(0xffffffffu, dot, o);

        const float score = (dot + cb) * inv_scale;

        if (score > m) {                     // warp-uniform
            const float rsc = __expf(m - score);
            l *= rsc;
            #pragma unroll
            for (int j = 0; j < 4; ++j) {
                acc[j].x *= rsc; acc[j].y *= rsc; acc[j].z *= rsc; acc[j].w *= rsc;
            }
            m = score;
        }
        const float wgt = __expf(score - m);
        l += wgt;
        #pragma unroll
        for (int j = 0; j < 4; ++j) {
            acc[j].x = fmaf(wgt, h4[j].x, acc[j].x);
            acc[j].y = fmaf(wgt, h4[j].y, acc[j].y);
            acc[j].z = fmaf(wgt, h4[j].z, acc[j].z);
            acc[j].w = fmaf(wgt, h4[j].w, acc[j].w);
        }

        #pragma unroll
        for (int j = 0; j < 4; ++j) h4[j] = n4[j];
    }

    // ---- deterministic block combine ----
    __shared__ float s_m[WARPS_B], s_l[WARPS_B], s_scale[WARPS_B];
    __shared__ float s_c[WARPS_B][H_];   // 16 KB
    if (lane == 0) { s_m[w] = m; s_l[w] = l; }
    __syncthreads();
    if (tid == 0) {
        float mb = s_m[0];
        #pragma unroll
        for (int i = 1; i < WARPS_B; ++i) mb = fmaxf(mb, s_m[i]);
        float lb = 0.f;
        #pragma unroll
        for (int i = 0; i < WARPS_B; ++i) {
            const float sc_ = __expf(s_m[i] - mb);
            s_scale[i] = sc_;
            lb = fmaf(sc_, s_l[i], lb);
        }
        const int idx = b * NCHUNK + chunk;
        g_pm[idx] = mb;
        g_pl[idx] = lb;
    }
    __syncthreads();

    const float sc_w = s_scale[w];
    #pragma unroll
    for (int j = 0; j < 4; ++j) {
        float4 v = acc[j];
        v.x *= sc_w; v.y *= sc_w; v.z *= sc_w; v.w *= sc_w;
        ((float4*)&s_c[w][j * 128])[lane] = v;
    }
    __syncthreads();

    float* gout = g_pc + (size_t)(b * NCHUNK + chunk) * H_;
    for (int hh = tid; hh < H_; hh += 256) {
        float t = 0.f;
        #pragma unroll
        for (int wi = 0; wi < WARPS_B; ++wi) t += s_c[wi][hh];
        gout[hh] = t;
    }
}

// ---------------------------------------------------------------------------
// Kernel C (fused combine + output GEMV): per batch b —
//   1) ctx[h] = invl * sum_c scale_c * pc[c][h]  into shared
//   2) out[b,a] = ctx . WvT[a] + bv[a], warp-per-output (32 outputs/warp)
// grid = B_, block = 256
__global__ __launch_bounds__(256) void finalize_kernel(
    const float* __restrict__ bv, float* __restrict__ out)
{
    const int b    = blockIdx.x;
    const int tid  = threadIdx.x;
    const int w    = tid >> 5;
    const int lane = tid & 31;

    __shared__ float s_scale[NCHUNK];
    __shared__ float s_ctx[H_];
    __shared__ float s_invl;

    if (tid == 0) {
        float mg = g_pm[b * NCHUNK];
        #pragma unroll 8
        for (int c = 1; c < NCHUNK; ++c) mg = fmaxf(mg, g_pm[b * NCHUNK + c]);
        float lg = 0.f;
        #pragma unroll 8
        for (int c = 0; c < NCHUNK; ++c) {
            const float sc_ = __expf(g_pm[b * NCHUNK + c] - mg);
            s_scale[c] = sc_;
            lg = fmaf(sc_, g_pl[b * NCHUNK + c], lg);
        }
        s_invl = 1.0f / lg;
    }
    __syncthreads();

    // ctx: each thread handles 2 h values (2 independent load chains per c)
    {
        const int h0 = tid;
        const int h1 = tid + 256;
        float t0 = 0.f, t1 = 0.f;
        #pragma unroll 8
        for (int c = 0; c < NCHUNK; ++c) {
            const float sc_ = s_scale[c];
            const float* row = g_pc + (size_t)(b * NCHUNK + c) * H_;
            t0 = fmaf(sc_, row[h0], t0);
            t1 = fmaf(sc_, row[h1], t1);
        }
        const float invl = s_invl;
        s_ctx[h0] = t0 * invl;
        s_ctx[h1] = t1 * invl;
    }
    __syncthreads();

    // output GEMV: warp w covers a = w, w+8, w+16, ... (32 outputs)
    #pragma unroll 4
    for (int oi = 0; oi < A_ / WARPS_B; ++oi) {
        const int a = oi * WARPS_B + w;
        const float* wr = g_WvT + a * H_;
        float acc = 0.f;
        #pragma unroll
        for (int j = 0; j < H_ / 32; ++j) {
            const int h = j * 32 + lane;
            acc = fmaf(s_ctx[h], wr[h], acc);
        }
        #pragma unroll
        for (int o = 16; o > 0; o >>= 1)
            acc += __shfl_xor_sync(0xffffffffu, acc, o);
        if (lane == 0) out[b * A_ + a] = acc + bv[a];
    }
}

// ---------------------------------------------------------------------------
extern "C" void kernel_launch(void* const* d_in, const int* in_sizes, int n_in,
                              void* d_out, int out_size)
{
    const float* x    = (const float*)d_in[0];
    const float* hist = (const float*)d_in[1];
    const float* Wq   = (const float*)d_in[2];
    const float* bq   = (const float*)d_in[3];
    const float* Wk   = (const float*)d_in[4];
    const float* bk   = (const float*)d_in[5];
    const float* Wv   = (const float*)d_in[6];
    const float* bv   = (const float*)d_in[7];
    float* out = (float*)d_out;

    q_kernel<<<B_, 256>>>(x, Wq, bq, bk);
    qt_kernel<<<(B_ * H_) / WARPS_B, 256>>>(Wk);
    wvT_kernel<<<dim3(A_ / 32, H_ / 32), dim3(32, 8)>>>(Wv);
    attn_pass_kernel<<<dim3(NCHUNK, B_), 256>>>(hist);
    finalize_kernel<<<B_, 256>>>(bv, out);
}

// round 7
// speedup vs baseline: 1.3300x; 1.3300x over previous
#include <cuda_runtime.h>
#include <math.h>

#define B_ 64
#define S_ 4096
#define H_ 512
#define A_ 256
#define IN_ 256
#define NCHUNK 32
#define CHUNK (S_ / NCHUNK)            // 128 rows per block
#define WARPS_B 8
#define ROWS_PER_WARP (CHUNK / WARPS_B) // 16

// Scratch (no allocations allowed) ------------------------------------------
__device__ float g_Q[B_ * A_];             // Q = x@Wq + bq
__device__ float g_qt[B_ * H_];            // folded query  q~ = Q @ Wk^T
__device__ float g_cst[B_];                // Q . bk
__device__ float g_pm[B_ * NCHUNK];        // per-chunk running max
__device__ float g_pl[B_ * NCHUNK];        // per-chunk exp-sum
__device__ float g_pc[B_ * NCHUNK * H_];   // per-chunk weighted hidden sum (4 MB)
__device__ float g_scale[B_ * NCHUNK];     // per-chunk softmax rescale
__device__ float g_invl[B_];               // 1 / global exp-sum
__device__ float g_ctx[B_ * H_];           // normalized context (pre-Wv)
__device__ float g_WvT[A_ * H_];           // transposed Wv (A-major)

// ---------------------------------------------------------------------------
// Kernel A1: Q = x@Wq + bq  and  cst[b] = Q[b] . bk   (8 chains, modest unroll)
__global__ __launch_bounds__(256) void q_kernel(
    const float* __restrict__ x, const float* __restrict__ Wq,
    const float* __restrict__ bq, const float* __restrict__ bk)
{
    const int b = blockIdx.x;
    const int a = threadIdx.x;
    __shared__ float shP[A_];

    const float* xr = x + b * IN_;
    float acc[8];
    #pragma unroll
    for (int k = 0; k < 8; ++k) acc[k] = 0.f;

    #pragma unroll 4
    for (int i = 0; i < IN_; i += 8) {
        #pragma unroll
        for (int k = 0; k < 8; ++k)
            acc[k] = fmaf(xr[i + k], Wq[(i + k) * A_ + a], acc[k]);
    }
    float q = 0.f;
    #pragma unroll
    for (int k = 0; k < 8; ++k) q += acc[k];
    q += bq[a];

    g_Q[b * A_ + a] = q;
    shP[a] = q * bk[a];
    __syncthreads();

    for (int s = 128; s > 0; s >>= 1) {
        if (a < s) shP[a] += shP[a + s];
        __syncthreads();
    }
    if (a == 0) g_cst[b] = shP[0];
}

// ---------------------------------------------------------------------------
// Kernel A2: q~[b,h] = sum_a Q[b,a] * Wk[h,a]  — one WARP per output element.
__global__ __launch_bounds__(256) void qt_kernel(const float* __restrict__ Wk)
{
    const int gw   = blockIdx.x * WARPS_B + (threadIdx.x >> 5);
    const int lane = threadIdx.x & 31;
    const int b = gw >> 9;          // /512
    const int h = gw & (H_ - 1);    // %512

    const float* wr = Wk + h * A_;
    const float* qr = g_Q + b * A_;
    float acc = 0.f;
    #pragma unroll
    for (int j = 0; j < A_ / 32; ++j) {
        const int a = j * 32 + lane;
        acc = fmaf(qr[a], wr[a], acc);
    }
    #pragma unroll
    for (int o = 16; o > 0; o >>= 1)
        acc += __shfl_xor_sync(0xffffffffu, acc, o);
    if (lane == 0) g_qt[b * H_ + h] = acc;
}

// ---------------------------------------------------------------------------
// Kernel A3: Wv transpose -> g_WvT[a][h]
__global__ __launch_bounds__(256) void wvT_kernel(const float* __restrict__ Wv)
{
    __shared__ float tile[32][33];
    const int a0 = blockIdx.x * 32;
    const int h0 = blockIdx.y * 32;
    const int tx = threadIdx.x;      // 0..31
    const int ty = threadIdx.y;      // 0..7

    #pragma unroll
    for (int i = 0; i < 4; ++i) {
        const int h = h0 + ty + i * 8;
        tile[ty + i * 8][tx] = Wv[h * A_ + a0 + tx];
    }
    __syncthreads();
    #pragma unroll
    for (int i = 0; i < 4; ++i) {
        const int a = a0 + ty + i * 8;
        g_WvT[a * H_ + h0 + tx] = tile[tx][ty + i * 8];
    }
}

// ---------------------------------------------------------------------------
// Kernel B: streaming online-softmax pass over history_h. (UNCHANGED from R6:
// measured 88.1 us @ 77.8% DRAM) grid = (NCHUNK, B_) = 2048 CTAs, 8 warps.
__global__ __launch_bounds__(256) void attn_pass_kernel(const float* __restrict__ hist)
{
    const int b     = blockIdx.y;
    const int chunk = blockIdx.x;
    const int tid   = threadIdx.x;
    const int w     = tid >> 5;
    const int lane  = tid & 31;

    float4 q4[4];
    const float4* qv = (const float4*)(g_qt + b * H_);
    #pragma unroll
    for (int j = 0; j < 4; ++j) q4[j] = qv[j * 32 + lane];

    const float cb = g_cst[b];
    const float inv_scale = 0.0625f; // 1/sqrt(256)

    float m = -INFINITY, l = 0.f;
    float4 acc[4];
    #pragma unroll
    for (int j = 0; j < 4; ++j) acc[j] = make_float4(0.f, 0.f, 0.f, 0.f);

    const int s0 = chunk * CHUNK + w * ROWS_PER_WARP;
    const float4* rowp = (const float4*)(hist + ((size_t)b * S_ + s0) * H_);
    const int row_stride4 = H_ / 4;

    float4 h4[4], n4[4];
    #pragma unroll
    for (int j = 0; j < 4; ++j) h4[j] = rowp[j * 32 + lane];

    for (int r = 0; r < ROWS_PER_WARP; ++r) {
        if (r < ROWS_PER_WARP - 1) {
            const float4* np = rowp + (size_t)(r + 1) * row_stride4;
            #pragma unroll
            for (int j = 0; j < 4; ++j) n4[j] = np[j * 32 + lane];
        }

        float dot = 0.f;
        #pragma unroll
        for (int j = 0; j < 4; ++j) {
            dot = fmaf(h4[j].x, q4[j].x, dot);
            dot = fmaf(h4[j].y, q4[j].y, dot);
            dot = fmaf(h4[j].z, q4[j].z, dot);
            dot = fmaf(h4[j].w, q4[j].w, dot);
        }
        #pragma unroll
        for (int o = 16; o > 0; o >>= 1)
            dot += __shfl_xor_sync(0xffffffffu, dot, o);

        const float score = (dot + cb) * inv_scale;

        if (score > m) {                     // warp-uniform
            const float rsc = __expf(m - score);
            l *= rsc;
            #pragma unroll
            for (int j = 0; j < 4; ++j) {
                acc[j].x *= rsc; acc[j].y *= rsc; acc[j].z *= rsc; acc[j].w *= rsc;
            }
            m = score;
        }
        const float wgt = __expf(score - m);
        l += wgt;
        #pragma unroll
        for (int j = 0; j < 4; ++j) {
            acc[j].x = fmaf(wgt, h4[j].x, acc[j].x);
            acc[j].y = fmaf(wgt, h4[j].y, acc[j].y);
            acc[j].z = fmaf(wgt, h4[j].z, acc[j].z);
            acc[j].w = fmaf(wgt, h4[j].w, acc[j].w);
        }

        #pragma unroll
        for (int j = 0; j < 4; ++j) h4[j] = n4[j];
    }

    // ---- deterministic block combine ----
    __shared__ float s_m[WARPS_B], s_l[WARPS_B], s_scale[WARPS_B];
    __shared__ float s_c[WARPS_B][H_];   // 16 KB
    if (lane == 0) { s_m[w] = m; s_l[w] = l; }
    __syncthreads();
    if (tid == 0) {
        float mb = s_m[0];
        #pragma unroll
        for (int i = 1; i < WARPS_B; ++i) mb = fmaxf(mb, s_m[i]);
        float lb = 0.f;
        #pragma unroll
        for (int i = 0; i < WARPS_B; ++i) {
            const float sc_ = __expf(s_m[i] - mb);
            s_scale[i] = sc_;
            lb = fmaf(sc_, s_l[i], lb);
        }
        const int idx = b * NCHUNK + chunk;
        g_pm[idx] = mb;
        g_pl[idx] = lb;
    }
    __syncthreads();

    const float sc_w = s_scale[w];
    #pragma unroll
    for (int j = 0; j < 4; ++j) {
        float4 v = acc[j];
        v.x *= sc_w; v.y *= sc_w; v.z *= sc_w; v.w *= sc_w;
        ((float4*)&s_c[w][j * 128])[lane] = v;
    }
    __syncthreads();

    float* gout = g_pc + (size_t)(b * NCHUNK + chunk) * H_;
    for (int hh = tid; hh < H_; hh += 256) {
        float t = 0.f;
        #pragma unroll
        for (int wi = 0; wi < WARPS_B; ++wi) t += s_c[wi][hh];
        gout[hh] = t;
    }
}

// ---------------------------------------------------------------------------
// Kernel C0: per-batch softmax stats -> g_scale[b][c], g_invl[b]
// grid = 1, block = 64 (thread per batch; 32 serial exps each — trivial)
__global__ __launch_bounds__(64) void stats_kernel()
{
    const int b = threadIdx.x;
    float mg = g_pm[b * NCHUNK];
    #pragma unroll 8
    for (int c = 1; c < NCHUNK; ++c) mg = fmaxf(mg, g_pm[b * NCHUNK + c]);
    float lg = 0.f;
    #pragma unroll 8
    for (int c = 0; c < NCHUNK; ++c) {
        const float sc_ = __expf(g_pm[b * NCHUNK + c] - mg);
        g_scale[b * NCHUNK + c] = sc_;
        lg = fmaf(sc_, g_pl[b * NCHUNK + c], lg);
    }
    g_invl[b] = 1.0f / lg;
}

// ---------------------------------------------------------------------------
// Kernel C1: combine chunk partials -> g_ctx. One THREAD per (b,h).
// grid = B_*2 = 128 blocks, block = 256. All loads coalesced across threads.
__global__ __launch_bounds__(256) void combine_kernel()
{
    const int b = blockIdx.x >> 1;
    const int h = (blockIdx.x & 1) * 256 + threadIdx.x;

    __shared__ float s_scale[NCHUNK];
    if (threadIdx.x < NCHUNK) s_scale[threadIdx.x] = g_scale[b * NCHUNK + threadIdx.x];
    __syncthreads();

    const float* base = g_pc + (size_t)b * NCHUNK * H_ + h;
    float t = 0.f;
    #pragma unroll 8
    for (int c = 0; c < NCHUNK; ++c)
        t = fmaf(s_scale[c], base[c * H_], t);
    g_ctx[b * H_ + h] = t * g_invl[b];
}

// ---------------------------------------------------------------------------
// Kernel C2: out[b,a] = ctx[b] . WvT[a] + bv[a] — one WARP per output.
// grid = 2048, block = 256. (R3-proven.)
__global__ __launch_bounds__(256) void out_kernel(
    const float* __restrict__ bv, float* __restrict__ out)
{
    const int gw   = blockIdx.x * WARPS_B + (threadIdx.x >> 5);
    const int lane = threadIdx.x & 31;
    const int b = gw >> 8;          // /256
    const int a = gw & (A_ - 1);    // %256

    const float* cr = g_ctx + b * H_;
    const float* wr = g_WvT + a * H_;
    float acc = 0.f;
    #pragma unroll
    for (int j = 0; j < H_ / 32; ++j) {
        const int h = j * 32 + lane;
        acc = fmaf(cr[h], wr[h], acc);
    }
    #pragma unroll
    for (int o = 16; o > 0; o >>= 1)
        acc += __shfl_xor_sync(0xffffffffu, acc, o);
    if (lane == 0) out[b * A_ + a] = acc + bv[a];
}

// ---------------------------------------------------------------------------
extern "C" void kernel_launch(void* const* d_in, const int* in_sizes, int n_in,
                              void* d_out, int out_size)
{
    const float* x    = (const float*)d_in[0];
    const float* hist = (const float*)d_in[1];
    const float* Wq   = (const float*)d_in[2];
    const float* bq   = (const float*)d_in[3];
    const float* Wk   = (const float*)d_in[4];
    const float* bk   = (const float*)d_in[5];
    const float* Wv   = (const float*)d_in[6];
    const float* bv   = (const float*)d_in[7];
    float* out = (float*)d_out;

    q_kernel<<<B_, 256>>>(x, Wq, bq, bk);
    qt_kernel<<<(B_ * H_) / WARPS_B, 256>>>(Wk);
    wvT_kernel<<<dim3(A_ / 32, H_ / 32), dim3(32, 8)>>>(Wv);
    attn_pass_kernel<<<dim3(NCHUNK, B_), 256>>>(hist);
    stats_kernel<<<1, 64>>>();
    combine_kernel<<<B_ * 2, 256>>>();
    out_kernel<<<(B_ * A_) / WARPS_B, 256>>>(bv, out);
}

// round 9
// speedup vs baseline: 1.4198x; 1.0675x over previous
#include <cuda_runtime.h>
#include <math.h>

#define B_ 64
#define S_ 4096
#define H_ 512
#define A_ 256
#define IN_ 256
#define NCHUNK 64
#define CHUNK (S_ / NCHUNK)            // 64 rows per block
#define WARPS_B 8
#define ROWS_PER_WARP (CHUNK / WARPS_B) // 8

#define QT_BLOCKS ((B_ * H_) / WARPS_B)   // 4096 blocks for qt
#define TR_BLOCKS ((A_ / 32) * (H_ / 32)) // 128 blocks for Wv transpose

// Scratch (no allocations allowed) ------------------------------------------
__device__ float g_Q[B_ * A_];             // Q = x@Wq + bq
__device__ float g_qt[B_ * H_];            // folded query  q~ = Q @ Wk^T
__device__ float g_cst[B_];                // Q . bk
__device__ float g_pm[B_ * NCHUNK];        // per-chunk running max
__device__ float g_pl[B_ * NCHUNK];        // per-chunk exp-sum
__device__ float g_pc[B_ * NCHUNK * H_];   // per-chunk weighted hidden sum (8 MB)
__device__ float g_ctx[B_ * H_];           // normalized context (pre-Wv)
__device__ float g_WvT[A_ * H_];           // transposed Wv (A-major)

// ---------------------------------------------------------------------------
// Kernel A1: Q = x@Wq + bq  and  cst[b] = Q[b] . bk   (8 chains, modest unroll)
__global__ __launch_bounds__(256) void q_kernel(
    const float* __restrict__ x, const float* __restrict__ Wq,
    const float* __restrict__ bq, const float* __restrict__ bk)
{
    const int b = blockIdx.x;
    const int a = threadIdx.x;
    __shared__ float shP[A_];

    const float* xr = x + b * IN_;
    float acc[8];
    #pragma unroll
    for (int k = 0; k < 8; ++k) acc[k] = 0.f;

    #pragma unroll 4
    for (int i = 0; i < IN_; i += 8) {
        #pragma unroll
        for (int k = 0; k < 8; ++k)
            acc[k] = fmaf(xr[i + k], Wq[(i + k) * A_ + a], acc[k]);
    }
    float q = 0.f;
    #pragma unroll
    for (int k = 0; k < 8; ++k) q += acc[k];
    q += bq[a];

    g_Q[b * A_ + a] = q;
    shP[a] = q * bk[a];
    __syncthreads();

    for (int s = 128; s > 0; s >>= 1) {
        if (a < s) shP[a] += shP[a + s];
        __syncthreads();
    }
    if (a == 0) g_cst[b] = shP[0];
}

// ---------------------------------------------------------------------------
// Kernel A2 (fused): blocks [0, QT_BLOCKS) compute q~ = Q @ Wk^T
//                    (one WARP per (b,h) output — 32768 warps total);
//                    blocks [QT_BLOCKS, QT_BLOCKS+TR_BLOCKS) transpose Wv.
__global__ __launch_bounds__(256) void prep_kernel(
    const float* __restrict__ Wk, const float* __restrict__ Wv)
{
    if (blockIdx.x < QT_BLOCKS) {
        // ---- qt: one warp per (b,h) output ----
        const int gw   = blockIdx.x * WARPS_B + (threadIdx.x >> 5); // 0..32767
        const int lane = threadIdx.x & 31;
        const int b = gw >> 9;          // /512
        const int h = gw & (H_ - 1);    // %512

        const float* wr = Wk + h * A_;
        const float* qr = g_Q + b * A_;
        float acc = 0.f;
        #pragma unroll
        for (int j = 0; j < A_ / 32; ++j) {
            const int a = j * 32 + lane;
            acc = fmaf(qr[a], wr[a], acc);
        }
        #pragma unroll
        for (int o = 16; o > 0; o >>= 1)
            acc += __shfl_xor_sync(0xffffffffu, acc, o);
        if (lane == 0) g_qt[b * H_ + h] = acc;
    } else {
        // ---- Wv transpose: 32x32 tile per block ----
        __shared__ float tile[32][33];
        const int bx = blockIdx.x - QT_BLOCKS; // 0..127
        const int a0 = (bx & 7) * 32;          // 8 tiles along A
        const int h0 = (bx >> 3) * 32;         // 16 tiles along H
        const int tx = threadIdx.x & 31;
        const int ty = threadIdx.x >> 5;       // 0..7

        #pragma unroll
        for (int i = 0; i < 4; ++i) {
            const int h = h0 + ty + i * 8;
            tile[ty + i * 8][tx] = Wv[h * A_ + a0 + tx];
        }
        __syncthreads();
        #pragma unroll
        for (int i = 0; i < 4; ++i) {
            const int a = a0 + ty + i * 8;
            g_WvT[a * H_ + h0 + tx] = tile[tx][ty + i * 8];
        }
    }
}

// ---------------------------------------------------------------------------
// Kernel B: streaming online-softmax pass over history_h.
// EXACT R5 configuration (measured 86.4us @ 80% DRAM): grid = (64, 64) = 4096
// CTAs, block = 256 (8 warps, 8 rows each), register q, pipelined row loads.
__global__ __launch_bounds__(256) void attn_pass_kernel(const float* __restrict__ hist)
{
    const int b     = blockIdx.y;
    const int chunk = blockIdx.x;
    const int tid   = threadIdx.x;
    const int w     = tid >> 5;
    const int lane  = tid & 31;

    float4 q4[4];
    const float4* qv = (const float4*)(g_qt + b * H_);
    #pragma unroll
    for (int j = 0; j < 4; ++j) q4[j] = qv[j * 32 + lane];

    const float cb = g_cst[b];
    const float inv_scale = 0.0625f; // 1/sqrt(256)

    float m = -INFINITY, l = 0.f;
    float4 acc[4];
    #pragma unroll
    for (int j = 0; j < 4; ++j) acc[j] = make_float4(0.f, 0.f, 0.f, 0.f);

    const int s0 = chunk * CHUNK + w * ROWS_PER_WARP;
    const float4* rowp = (const float4*)(hist + ((size_t)b * S_ + s0) * H_);
    const int row_stride4 = H_ / 4;

    float4 h4[4], n4[4];
    #pragma unroll
    for (int j = 0; j < 4; ++j) h4[j] = rowp[j * 32 + lane];

    #pragma unroll
    for (int r = 0; r < ROWS_PER_WARP; ++r) {
        if (r < ROWS_PER_WARP - 1) {
            const float4* np = rowp + (size_t)(r + 1) * row_stride4;
            #pragma unroll
            for (int j = 0; j < 4; ++j) n4[j] = np[j * 32 + lane];
        }

        float dot = 0.f;
        #pragma unroll
        for (int j = 0; j < 4; ++j) {
            dot = fmaf(h4[j].x, q4[j].x, dot);
            dot = fmaf(h4[j].y, q4[j].y, dot);
            dot = fmaf(h4[j].z, q4[j].z, dot);
            dot = fmaf(h4[j].w, q4[j].w, dot);
        }
        #pragma unroll
        for (int o = 16; o > 0; o >>= 1)
            dot += __shfl_xor_sync(0xffffffffu, dot, o);

        const float score = (dot + cb) * inv_scale;

        if (score > m) {                     // warp-uniform
            const float rsc = __expf(m - score);
            l *= rsc;
            #pragma unroll
            for (int j = 0; j < 4; ++j) {
                acc[j].x *= rsc; acc[j].y *= rsc; acc[j].z *= rsc; acc[j].w *= rsc;
            }
            m = score;
        }
        const float wgt = __expf(score - m);
        l += wgt;
        #pragma unroll
        for (int j = 0; j < 4; ++j) {
            acc[j].x = fmaf(wgt, h4[j].x, acc[j].x);
            acc[j].y = fmaf(wgt, h4[j].y, acc[j].y);
            acc[j].z = fmaf(wgt, h4[j].z, acc[j].z);
            acc[j].w = fmaf(wgt, h4[j].w, acc[j].w);
        }

        #pragma unroll
        for (int j = 0; j < 4; ++j) h4[j] = n4[j];
    }

    // ---- deterministic block combine ----
    __shared__ float s_m[WARPS_B], s_l[WARPS_B], s_scale[WARPS_B];
    __shared__ float s_c[WARPS_B][H_];   // 16 KB
    if (lane == 0) { s_m[w] = m; s_l[w] = l; }
    __syncthreads();
    if (tid == 0) {
        float mb = s_m[0];
        #pragma unroll
        for (int i = 1; i < WARPS_B; ++i) mb = fmaxf(mb, s_m[i]);
        float lb = 0.f;
        #pragma unroll
        for (int i = 0; i < WARPS_B; ++i) {
            const float sc_ = __expf(s_m[i] - mb);
            s_scale[i] = sc_;
            lb = fmaf(sc_, s_l[i], lb);
        }
        const int idx = b * NCHUNK + chunk;
        g_pm[idx] = mb;
        g_pl[idx] = lb;
    }
    __syncthreads();

    const float sc_w = s_scale[w];
    #pragma unroll
    for (int j = 0; j < 4; ++j) {
        float4 v = acc[j];
        v.x *= sc_w; v.y *= sc_w; v.z *= sc_w; v.w *= sc_w;
        ((float4*)&s_c[w][j * 128])[lane] = v;
    }
    __syncthreads();

    float* gout = g_pc + (size_t)(b * NCHUNK + chunk) * H_;
    for (int hh = tid; hh < H_; hh += 256) {
        float t = 0.f;
        #pragma unroll
        for (int wi = 0; wi < WARPS_B; ++wi) t += s_c[wi][hh];
        gout[hh] = t;
    }
}

// ---------------------------------------------------------------------------
// Kernel C1: combine chunk partials -> g_ctx, with softmax stats computed
// inline by warp 0 of each block (cheap redundant work, deterministic).
// grid = B_*2 = 128 blocks, block = 256. One THREAD per (b,h); coalesced.
__global__ __launch_bounds__(256) void combine_kernel()
{
    const int b = blockIdx.x >> 1;
    const int h = (blockIdx.x & 1) * 256 + threadIdx.x;

    __shared__ float s_scale[NCHUNK];
    __shared__ float s_invl;

    if (threadIdx.x < 32) {
        const int lane = threadIdx.x;
        const float m0 = g_pm[b * NCHUNK + lane];
        const float m1 = g_pm[b * NCHUNK + lane + 32];
        const float l0 = g_pl[b * NCHUNK + lane];
        const float l1 = g_pl[b * NCHUNK + lane + 32];
        float mm = fmaxf(m0, m1);
        #pragma unroll
        for (int o = 16; o > 0; o >>= 1)
            mm = fmaxf(mm, __shfl_xor_sync(0xffffffffu, mm, o));
        const float sc0 = __expf(m0 - mm);
        const float sc1 = __expf(m1 - mm);
        float ls = fmaf(sc0, l0, sc1 * l1);
        #pragma unroll
        for (int o = 16; o > 0; o >>= 1)
            ls += __shfl_xor_sync(0xffffffffu, ls, o);
        s_scale[lane]      = sc0;
        s_scale[lane + 32] = sc1;
        if (lane == 0) s_invl = 1.0f / ls;
    }
    __syncthreads();

    const float* base = g_pc + (size_t)b * NCHUNK * H_ + h;
    float t = 0.f;
    #pragma unroll 8
    for (int c = 0; c < NCHUNK; ++c)
        t = fmaf(s_scale[c], base[(size_t)c * H_], t);
    g_ctx[b * H_ + h] = t * s_invl;
}

// ---------------------------------------------------------------------------
// Kernel C2: out[b,a] = ctx[b] . WvT[a] + bv[a] — one WARP per output.
// grid = 2048, block = 256. (R3/R7-proven.)
__global__ __launch_bounds__(256) void out_kernel(
    const float* __restrict__ bv, float* __restrict__ out)
{
    const int gw   = blockIdx.x * WARPS_B + (threadIdx.x >> 5);
    const int lane = threadIdx.x & 31;
    const int b = gw >> 8;          // /256
    const int a = gw & (A_ - 1);    // %256

    const float* cr = g_ctx + b * H_;
    const float* wr = g_WvT + a * H_;
    float acc = 0.f;
    #pragma unroll
    for (int j = 0; j < H_ / 32; ++j) {
        const int h = j * 32 + lane;
        acc = fmaf(cr[h], wr[h], acc);
    }
    #pragma unroll
    for (int o = 16; o > 0; o >>= 1)
        acc += __shfl_xor_sync(0xffffffffu, acc, o);
    if (lane == 0) out[b * A_ + a] = acc + bv[a];
}

// ---------------------------------------------------------------------------
extern "C" void kernel_launch(void* const* d_in, const int* in_sizes, int n_in,
                              void* d_out, int out_size)
{
    const float* x    = (const float*)d_in[0];
    const float* hist = (const float*)d_in[1];
    const float* Wq   = (const float*)d_in[2];
    const float* bq   = (const float*)d_in[3];
    const float* Wk   = (const float*)d_in[4];
    const float* bk   = (const float*)d_in[5];
    const float* Wv   = (const float*)d_in[6];
    const float* bv   = (const float*)d_in[7];
    float* out = (float*)d_out;

    q_kernel<<<B_, 256>>>(x, Wq, bq, bk);
    prep_kernel<<<QT_BLOCKS + TR_BLOCKS, 256>>>(Wk, Wv);
    attn_pass_kernel<<<dim3(NCHUNK, B_), 256>>>(hist);
    combine_kernel<<<B_ * 2, 256>>>();
    out_kernel<<<(B_ * A_) / WARPS_B, 256>>>(bv, out);
}